// round 1
// baseline (speedup 1.0000x reference)
#include <cuda_runtime.h>
#include <cstdint>

// ---------------------------------------------------------------------------
// Scratch (device globals — no allocation allowed)
// ---------------------------------------------------------------------------
__device__ float g_h1[16*64*128*128];          // enc1 out / dec2 out (reused)
__device__ float g_h2[16*128*64*64];           // enc2 out / dec1 out (reused)
__device__ float g_h3[16*256*64*64];           // enc3 out
__device__ float g_z [16*256*64*64];           // enc4 out (z) / quantized NCHW (reused)
__device__ float g_resid[65536*256];
__device__ float g_qsum [65536*256];
__device__ unsigned long long g_best[65536];
__device__ double g_loss[4];
__device__ float g_cnorm[4*1024];
__device__ float g_w4p[64*16*8];               // dec_w4 repacked [ci][16][co(pad 8)]
__device__ float g_d3[16*64*256*256];          // dec3 out (268 MB)

// ---------------------------------------------------------------------------
// Direct conv, NCHW. Block: 128 thr = 16 px-cols x 8 cout-groups.
// Tile: 16(ox) x 4(oy) pixels, 64 couts. Thread: 4 px x 8 couts.
// ---------------------------------------------------------------------------
template<int K, int S>
__global__ __launch_bounds__(128)
void conv2d_tiled(const float* __restrict__ in, const float* __restrict__ w,
                  const float* __restrict__ bias, float* __restrict__ out,
                  int Cin, int H, int W, int Cout, int Ho, int Wo,
                  int pad, int relu)
{
    constexpr int CIN_T = 8;
    constexpr int IH = 3*S + K;
    constexpr int IW = 15*S + K;
    constexpr int KK = K*K;
    __shared__ __align__(16) float s_in[CIN_T*IH*IW];
    __shared__ __align__(16) float s_w [CIN_T*KK*64];

    const int tid = threadIdx.x;
    const int px  = tid & 15;
    const int cg  = tid >> 4;              // 0..7
    const int hb  = Ho >> 2;
    const int b   = blockIdx.y / hb;
    const int oy0 = (blockIdx.y % hb) * 4;
    const int ox0 = blockIdx.x * 16;
    const int co0 = blockIdx.z * 64;
    const int iy0 = oy0*S - pad;
    const int ix0 = ox0*S - pad;

    float acc[4][8];
#pragma unroll
    for (int p = 0; p < 4; p++)
#pragma unroll
        for (int c = 0; c < 8; c++) acc[p][c] = 0.f;

    for (int ci0 = 0; ci0 < Cin; ci0 += CIN_T) {
        // ---- load input tile (zero-padded) ----
        for (int idx = tid; idx < CIN_T*IH*IW; idx += 128) {
            int ci  = idx / (IH*IW);
            int rem = idx % (IH*IW);
            int r   = rem / IW, c = rem % IW;
            int iy  = iy0 + r, ix = ix0 + c;
            float v = 0.f;
            if ((unsigned)iy < (unsigned)H && (unsigned)ix < (unsigned)W &&
                (ci0 + ci) < Cin)
                v = in[((b*Cin + ci0 + ci)*H + iy)*W + ix];
            s_in[idx] = v;
        }
        // ---- load weights as [ci][kk][co] (co contiguous for float4) ----
        for (int idx = tid; idx < CIN_T*KK*64; idx += 128) {
            int co  = idx & 63;
            int rem = idx >> 6;
            int kk  = rem % KK;
            int ci  = rem / KK;
            float v = 0.f;
            if ((ci0 + ci) < Cin)
                v = w[((co0 + co)*Cin + ci0 + ci)*KK + kk];
            s_w[idx] = v;
        }
        __syncthreads();

        for (int ci = 0; ci < CIN_T; ci++) {
#pragma unroll
            for (int kh = 0; kh < K; kh++) {
#pragma unroll
                for (int kw = 0; kw < K; kw++) {
                    const float4* wp =
                        (const float4*)(s_w + ((ci*KK + kh*K + kw) << 6) + (cg << 3));
                    float4 w0 = wp[0], w1 = wp[1];
#pragma unroll
                    for (int p = 0; p < 4; p++) {
                        float iv = s_in[(ci*IH + p*S + kh)*IW + px*S + kw];
                        acc[p][0] += iv*w0.x; acc[p][1] += iv*w0.y;
                        acc[p][2] += iv*w0.z; acc[p][3] += iv*w0.w;
                        acc[p][4] += iv*w1.x; acc[p][5] += iv*w1.y;
                        acc[p][6] += iv*w1.z; acc[p][7] += iv*w1.w;
                    }
                }
            }
        }
        __syncthreads();
    }

#pragma unroll
    for (int c = 0; c < 8; c++) {
        int co = co0 + (cg << 3) + c;
        float bv = bias[co];
#pragma unroll
        for (int p = 0; p < 4; p++) {
            float v = acc[p][c] + bv;
            if (relu) v = fmaxf(v, 0.f);
            out[((b*Cout + co)*Ho + oy0 + p)*Wo + ox0 + px] = v;
        }
    }
}

// ---------------------------------------------------------------------------
// ConvTranspose2d, k=4, s=2, p=1 via parity-tap decomposition.
// Torch weight layout (Cin, Cout, 4, 4): y[co,oy,ox] = sum x[ci,(oy+1-ky)/2,(ox+1-kx)/2]*w[ci,co,ky,kx]
// Block: COG*PXW threads; tile PXW(ox) x 4(oy), COG*8 couts; thread 4 px x 8 co.
// act: 0 = relu, 1 = tanh
// ---------------------------------------------------------------------------
template<int COG, int PXW, bool PACKED>
__global__ __launch_bounds__(COG*PXW)
void convT_tiled(const float* __restrict__ in, const float* __restrict__ w,
                 const float* __restrict__ bias, float* __restrict__ out,
                 int Cin, int Hin, int Win, int CoutW, int CoutReal, int act)
{
    constexpr int CIN_T = 8;
    constexpr int IH = 4;
    constexpr int IW = PXW/2 + 2;
    constexpr int NCO = COG*8;
    __shared__ __align__(16) float s_in[CIN_T*IH*IW];
    __shared__ __align__(16) float s_w [CIN_T*16*NCO];

    const int tid = threadIdx.x;
    const int px  = tid % PXW;
    const int cg  = tid / PXW;
    const int Ho = Hin*2, Wo = Win*2;
    const int hb  = Ho >> 2;
    const int b   = blockIdx.y / hb;
    const int oy0 = (blockIdx.y % hb) * 4;
    const int ox0 = blockIdx.x * PXW;
    const int co0 = blockIdx.z * NCO;
    const int m0  = oy0 >> 1;
    const int mx0 = ox0 >> 1;

    const int ox = ox0 + px;
    const int ex = ox & 1;
    const int mx = ox >> 1;
    int kxt[2], cxt[2];
    if (ex == 0) { kxt[0]=1; cxt[0]=mx-mx0+1; kxt[1]=3; cxt[1]=mx-mx0;   }
    else         { kxt[0]=0; cxt[0]=mx-mx0+2; kxt[1]=2; cxt[1]=mx-mx0+1; }

    float acc[4][8];
#pragma unroll
    for (int p = 0; p < 4; p++)
#pragma unroll
        for (int c = 0; c < 8; c++) acc[p][c] = 0.f;

    for (int ci0 = 0; ci0 < Cin; ci0 += CIN_T) {
        // input tile: rows m0-1..m0+2, cols mx0-1..mx0+IW-2 (zero padded)
        for (int idx = tid; idx < CIN_T*IH*IW; idx += COG*PXW) {
            int ci  = idx / (IH*IW);
            int rem = idx % (IH*IW);
            int r = rem / IW, c = rem % IW;
            int iy = m0 - 1 + r, ix = mx0 - 1 + c;
            float v = 0.f;
            if ((unsigned)iy < (unsigned)Hin && (unsigned)ix < (unsigned)Win)
                v = in[((b*Cin + ci0 + ci)*Hin + iy)*Win + ix];
            s_in[idx] = v;
        }
        // weights -> s_w[ci][kk][co]
        for (int idx = tid; idx < CIN_T*16*NCO; idx += COG*PXW) {
            int co  = idx % NCO;
            int rem = idx / NCO;
            int kk  = rem % 16;
            int ci  = rem / 16;
            float v;
            if (PACKED) v = w[((ci0 + ci)*16 + kk)*8 + co];
            else        v = w[((ci0 + ci)*CoutW + co0 + co)*16 + kk];
            s_w[idx] = v;
        }
        __syncthreads();

        for (int ci = 0; ci < CIN_T; ci++) {
#pragma unroll
            for (int ey = 0; ey < 2; ey++) {
#pragma unroll
                for (int jy = 0; jy < 2; jy++) {
                    const int ky    = (ey==0) ? (jy==0 ? 1 : 3) : (jy==0 ? 0 : 2);
                    const int rbase = (ey==0) ? (jy==0 ? 1 : 0) : (jy==0 ? 2 : 1);
#pragma unroll
                    for (int jx = 0; jx < 2; jx++) {
                        int kk = ky*4 + kxt[jx];
                        const float4* wp =
                            (const float4*)(s_w + (ci*16 + kk)*NCO + cg*8);
                        float4 w0 = wp[0], w1 = wp[1];
#pragma unroll
                        for (int ph = 0; ph < 2; ph++) {
                            int p   = ey + ph*2;
                            int row = ph + rbase;
                            float iv = s_in[(ci*IH + row)*IW + cxt[jx]];
                            acc[p][0] += iv*w0.x; acc[p][1] += iv*w0.y;
                            acc[p][2] += iv*w0.z; acc[p][3] += iv*w0.w;
                            acc[p][4] += iv*w1.x; acc[p][5] += iv*w1.y;
                            acc[p][6] += iv*w1.z; acc[p][7] += iv*w1.w;
                        }
                    }
                }
            }
        }
        __syncthreads();
    }

#pragma unroll
    for (int c = 0; c < 8; c++) {
        int co = co0 + cg*8 + c;
        if (co >= CoutReal) continue;
        float bv = bias[co];
#pragma unroll
        for (int p = 0; p < 4; p++) {
            float v = acc[p][c] + bv;
            v = act ? tanhf(v) : fmaxf(v, 0.f);
            out[((b*CoutReal + co)*Ho + oy0 + p)*Wo + ox] = v;
        }
    }
}

// ---------------------------------------------------------------------------
// RVQ: GEMM (65536x256) x (1024x256)^T with fused argmin of (|c|^2 - 2 s).
// Block 256 thr, tile 128x128, thread 8x8.
// ---------------------------------------------------------------------------
__device__ __forceinline__ unsigned long long enc_key(float d, int n) {
    unsigned u = __float_as_uint(d);
    u = (u & 0x80000000u) ? ~u : (u | 0x80000000u);
    return ((unsigned long long)u << 32) | (unsigned)n;
}

__global__ __launch_bounds__(256)
void vq_gemm_argmin(const float* __restrict__ R, const float* __restrict__ cb,
                    const float* __restrict__ cn, unsigned long long* __restrict__ best)
{
    __shared__ __align__(16) float sA[16][128];
    __shared__ __align__(16) float sB[16][132];
    __shared__ unsigned long long sMin[128];

    const int tid = threadIdx.x;
    const int tx = tid & 15, ty = tid >> 4;
    const int m0 = blockIdx.x << 7, n0 = blockIdx.y << 7;

    float acc[8][8];
#pragma unroll
    for (int i = 0; i < 8; i++)
#pragma unroll
        for (int j = 0; j < 8; j++) acc[i][j] = 0.f;

    for (int k0 = 0; k0 < 256; k0 += 16) {
#pragma unroll
        for (int v = 0; v < 2; v++) {
            int u = tid*2 + v;
            int row = u >> 2, kq = u & 3;
            float4 a4 = *(const float4*)(R  + (size_t)(m0 + row)*256 + k0 + kq*4);
            sA[kq*4+0][row] = a4.x; sA[kq*4+1][row] = a4.y;
            sA[kq*4+2][row] = a4.z; sA[kq*4+3][row] = a4.w;
            float4 b4 = *(const float4*)(cb + (size_t)(n0 + row)*256 + k0 + kq*4);
            sB[kq*4+0][row] = b4.x; sB[kq*4+1][row] = b4.y;
            sB[kq*4+2][row] = b4.z; sB[kq*4+3][row] = b4.w;
        }
        __syncthreads();
#pragma unroll
        for (int kk = 0; kk < 16; kk++) {
            float4 a0 = *(const float4*)&sA[kk][ty*8];
            float4 a1 = *(const float4*)&sA[kk][ty*8+4];
            float4 b0 = *(const float4*)&sB[kk][tx*8];
            float4 b1 = *(const float4*)&sB[kk][tx*8+4];
            float a[8] = {a0.x,a0.y,a0.z,a0.w,a1.x,a1.y,a1.z,a1.w};
            float bb[8] = {b0.x,b0.y,b0.z,b0.w,b1.x,b1.y,b1.z,b1.w};
#pragma unroll
            for (int i = 0; i < 8; i++)
#pragma unroll
                for (int j = 0; j < 8; j++) acc[i][j] += a[i]*bb[j];
        }
        __syncthreads();
    }

    float cnv[8];
#pragma unroll
    for (int j = 0; j < 8; j++) cnv[j] = cn[n0 + tx*8 + j];

    if (tid < 128) sMin[tid] = ~0ull;
    __syncthreads();

#pragma unroll
    for (int i = 0; i < 8; i++) {
        float bd = 3.402823466e38f; int bn = n0 + tx*8;
#pragma unroll
        for (int j = 0; j < 8; j++) {
            float d = cnv[j] - 2.f*acc[i][j];
            if (d < bd) { bd = d; bn = n0 + tx*8 + j; }
        }
        atomicMin(&sMin[ty*8 + i], enc_key(bd, bn));
    }
    __syncthreads();
    if (tid < 128) atomicMin(&best[m0 + tid], sMin[tid]);
}

__global__ void init_best(unsigned long long* best) {
    int i = blockIdx.x*256 + threadIdx.x;
    if (i < 65536) best[i] = ~0ull;
}

// one warp per token: q = cb[idx]; loss += |q-r|^2; qsum += q; r -= q; write index
__global__ __launch_bounds__(256)
void vq_update(const unsigned long long* __restrict__ best, const float* __restrict__ cb,
               float* __restrict__ resid, float* __restrict__ qsum,
               float* __restrict__ idx_out, int stage, double* __restrict__ lossAcc)
{
    int gw   = (blockIdx.x*256 + threadIdx.x) >> 5;
    int lane = threadIdx.x & 31;
    if (gw >= 65536) return;
    int n = (int)(best[gw] & 0xFFFFFFFFull);
    const float4* q4 = (const float4*)(cb + (size_t)n*256);
    float4* r4 = (float4*)(resid + (size_t)gw*256);
    float4* s4 = (float4*)(qsum  + (size_t)gw*256);
    float ls = 0.f;
#pragma unroll
    for (int c = lane; c < 64; c += 32) {
        float4 q = q4[c], r = r4[c], s = s4[c];
        float dx = q.x-r.x, dy = q.y-r.y, dz = q.z-r.z, dw = q.w-r.w;
        ls += dx*dx + dy*dy + dz*dz + dw*dw;
        s.x += q.x; s.y += q.y; s.z += q.z; s.w += q.w;
        r.x -= q.x; r.y -= q.y; r.z -= q.z; r.w -= q.w;
        s4[c] = s; r4[c] = r;
    }
#pragma unroll
    for (int o = 16; o; o >>= 1) ls += __shfl_down_sync(0xffffffffu, ls, o);
    if (lane == 0) {
        atomicAdd(lossAcc + stage, (double)ls);
        idx_out[(gw >> 12)*16384 + stage*4096 + (gw & 4095)] = (float)n;
    }
}

// ---------------------------------------------------------------------------
// Small helpers
// ---------------------------------------------------------------------------
__global__ void cnorm_kernel(const float* __restrict__ cb, float* __restrict__ cn) {
    int row  = (blockIdx.x*blockDim.x + threadIdx.x) >> 5;
    int lane = threadIdx.x & 31;
    if (row >= 4096) return;
    const float* p = cb + (size_t)row*256;
    float s = 0.f;
    for (int c = lane; c < 256; c += 32) { float v = p[c]; s += v*v; }
#pragma unroll
    for (int o = 16; o; o >>= 1) s += __shfl_down_sync(0xffffffffu, s, o);
    if (!lane) cn[row] = s;
}

__global__ void repack_w4(const float* __restrict__ w, float* __restrict__ wp) {
    int idx = blockIdx.x*256 + threadIdx.x;          // 64*16*8 = 8192
    if (idx >= 64*16*8) return;
    int co = idx & 7, rem = idx >> 3;
    int kk = rem & 15, ci = rem >> 4;
    wp[idx] = (co < 3) ? w[(ci*3 + co)*16 + kk] : 0.f;
}

__global__ void zero_loss(double* l) { if (threadIdx.x < 4) l[threadIdx.x] = 0.0; }

__global__ void write_loss(const double* __restrict__ l, float* __restrict__ o) {
    if (threadIdx.x < 4)
        o[threadIdx.x] = (float)(l[threadIdx.x] * (1.0/(65536.0*256.0)));
}

// z (16,256,4096) NCHW -> tokens (65536,256); zero qsum
__global__ void z_to_tokens(const float* __restrict__ z,
                            float* __restrict__ resid, float* __restrict__ qsum)
{
    __shared__ float t[32][33];
    int b  = blockIdx.z;
    int s0 = blockIdx.x*32;
    int c0 = blockIdx.y*32;
    int x  = threadIdx.x;
    for (int y = threadIdx.y; y < 32; y += 8)
        t[y][x] = z[((size_t)b*256 + c0 + y)*4096 + s0 + x];
    __syncthreads();
    for (int y = threadIdx.y; y < 32; y += 8) {
        size_t o = ((size_t)b*4096 + s0 + y)*256 + c0 + x;
        resid[o] = t[x][y];
        qsum[o]  = 0.f;
    }
}

// tokens -> NCHW (two destinations: dec1 input + quantized output)
__global__ void tokens_to_z(const float* __restrict__ qsum,
                            float* __restrict__ z1, float* __restrict__ z2)
{
    __shared__ float t[32][33];
    int b  = blockIdx.z;
    int c0 = blockIdx.x*32;
    int s0 = blockIdx.y*32;
    int x  = threadIdx.x;
    for (int y = threadIdx.y; y < 32; y += 8)
        t[y][x] = qsum[((size_t)b*4096 + s0 + y)*256 + c0 + x];
    __syncthreads();
    for (int y = threadIdx.y; y < 32; y += 8) {
        float v = t[x][y];
        size_t o = ((size_t)b*256 + c0 + y)*4096 + s0 + x;
        z1[o] = v; z2[o] = v;
    }
}

// ---------------------------------------------------------------------------
// Launch
// ---------------------------------------------------------------------------
extern "C" void kernel_launch(void* const* d_in, const int* in_sizes, int n_in,
                              void* d_out, int out_size)
{
    const float* x   = (const float*)d_in[0];
    const float* ew1 = (const float*)d_in[1];  const float* eb1 = (const float*)d_in[2];
    const float* ew2 = (const float*)d_in[3];  const float* eb2 = (const float*)d_in[4];
    const float* ew3 = (const float*)d_in[5];  const float* eb3 = (const float*)d_in[6];
    const float* ew4 = (const float*)d_in[7];  const float* eb4 = (const float*)d_in[8];
    const float* cbs = (const float*)d_in[9];
    const float* dw1 = (const float*)d_in[10]; const float* db1 = (const float*)d_in[11];
    const float* dw2 = (const float*)d_in[12]; const float* db2 = (const float*)d_in[13];
    const float* dw3 = (const float*)d_in[14]; const float* db3 = (const float*)d_in[15];
    const float* dw4 = (const float*)d_in[16]; const float* db4 = (const float*)d_in[17];
    float* out = (float*)d_out;

    float *h1, *h2, *h3, *z, *resid, *qsum, *cnorm, *w4p, *d3;
    unsigned long long* best; double* loss;
    cudaGetSymbolAddress((void**)&h1,   g_h1);
    cudaGetSymbolAddress((void**)&h2,   g_h2);
    cudaGetSymbolAddress((void**)&h3,   g_h3);
    cudaGetSymbolAddress((void**)&z,    g_z);
    cudaGetSymbolAddress((void**)&resid,g_resid);
    cudaGetSymbolAddress((void**)&qsum, g_qsum);
    cudaGetSymbolAddress((void**)&best, g_best);
    cudaGetSymbolAddress((void**)&loss, g_loss);
    cudaGetSymbolAddress((void**)&cnorm,g_cnorm);
    cudaGetSymbolAddress((void**)&w4p,  g_w4p);
    cudaGetSymbolAddress((void**)&d3,   g_d3);

    // output layout: recon | indices | commit_loss | quantized
    float* recO   = out;
    float* idxO   = out + 12582912;                 // 16*3*512*512
    float* lossO  = idxO + 262144;                  // 16*4*64*64
    float* quantO = lossO + 4;

    // prep
    repack_w4  <<<32, 256>>>(dw4, w4p);
    cnorm_kernel<<<512, 256>>>(cbs, cnorm);
    zero_loss  <<<1, 32>>>(loss);

    // ---- encoder ----
    conv2d_tiled<4,2><<<dim3(8, 32*16, 1), 128>>>(x,  ew1, eb1, h1,   3, 256, 256,  64, 128, 128, 1, 1);
    conv2d_tiled<4,2><<<dim3(4, 16*16, 2), 128>>>(h1, ew2, eb2, h2,  64, 128, 128, 128,  64,  64, 1, 1);
    conv2d_tiled<3,1><<<dim3(4, 16*16, 4), 128>>>(h2, ew3, eb3, h3, 128,  64,  64, 256,  64,  64, 1, 1);
    conv2d_tiled<3,1><<<dim3(4, 16*16, 4), 128>>>(h3, ew4, eb4, z,  256,  64,  64, 256,  64,  64, 1, 0);

    // ---- residual VQ ----
    z_to_tokens<<<dim3(128, 8, 16), dim3(32, 8)>>>(z, resid, qsum);
    for (int s = 0; s < 4; s++) {
        init_best     <<<256, 256>>>(best);
        vq_gemm_argmin<<<dim3(512, 8), 256>>>(resid, cbs + (size_t)s*1024*256,
                                              cnorm + s*1024, best);
        vq_update     <<<8192, 256>>>(best, cbs + (size_t)s*1024*256,
                                      resid, qsum, idxO, s, loss);
    }
    write_loss <<<1, 32>>>(loss, lossO);
    tokens_to_z<<<dim3(8, 128, 16), dim3(32, 8)>>>(qsum, z, quantO);

    // ---- decoder ----
    conv2d_tiled<3,1><<<dim3(4, 16*16, 2), 128>>>(z, dw1, db1, h2, 256, 64, 64, 128, 64, 64, 1, 1);
    convT_tiled<8,  16, false><<<dim3( 8,  32*16, 1), 128>>>(h2, dw2, db2, h1, 128,  64,  64, 64, 64, 0);
    convT_tiled<8,  16, false><<<dim3(16,  64*16, 1), 128>>>(h1, dw3, db3, d3,  64, 128, 128, 64, 64, 0);
    convT_tiled<1, 128, true ><<<dim3( 4, 128*16, 1), 128>>>(d3, w4p, db4, recO, 64, 256, 256,  8,  3, 1);
}